// round 14
// baseline (speedup 1.0000x reference)
#include <cuda_runtime.h>
#include <cuda_fp16.h>
#include <math.h>

typedef unsigned int u32;
typedef unsigned long long u64;
typedef __half f16;

#define CB 4
#define CS 2048
#define CD 1024
#define CH 8
#define CHID 4096

// ---------------- scratch (device globals) ----------------
// Single fp16 plane per tensor. All K-major. uint4 arrays for 16B align (cp.async).
#define DECL_ONE(name, n) __device__ uint4 name##_h_[(size_t)(n) / 8];

DECL_ONE(g_X,  (size_t)CB*CS*CD)
DECL_ONE(g_Wq, (size_t)CH*CD*CD)
DECL_ONE(g_Wk, (size_t)CH*CD*CD)
DECL_ONE(g_Wv, (size_t)CH*CD*CD)
DECL_ONE(g_Wo, (size_t)CD*CH*CD)
DECL_ONE(g_W1, (size_t)CHID*CD)
DECL_ONE(g_W2, (size_t)CHID*CHID)
DECL_ONE(g_W3, (size_t)CHID*CHID)
DECL_ONE(g_W4, (size_t)CD*CHID)
DECL_ONE(g_Q,  (size_t)CH*CB*CS*CD)     // [(h,b)][s][d]
DECL_ONE(g_K,  (size_t)CH*CB*CS*CD)
DECL_ONE(g_VT, (size_t)CH*CB*CD*CS)     // [h][b][e][t]
DECL_ONE(g_SCb,(size_t)CH*CB*CS*CS)     // scores f16
DECL_ONE(g_AT, (size_t)CH*CB*CS*CS)     // attn f16
DECL_ONE(g_ZC, (size_t)CB*CS*CH*CD)     // head-concat f16
DECL_ONE(g_Y1, (size_t)CB*CS*CHID)
DECL_ONE(g_Y2, (size_t)CB*CS*CHID)
DECL_ONE(g_ZN, (size_t)CB*CS*CD)
__device__ float g_AO[(size_t)CB*CS*CD];
__device__ float g_Z1[(size_t)CB*CS*CD];

// ---------------- helpers ----------------
__device__ __forceinline__ u32 smem_u32(const void* p){
    u32 a; asm("{ .reg .u64 t; cvta.to.shared.u64 t, %1; cvt.u32.u64 %0, t; }":"=r"(a):"l"(p)); return a;
}
__device__ __forceinline__ void cpa16(u32 dst, const void* src){
    asm volatile("cp.async.cg.shared.global [%0], [%1], 16;" :: "r"(dst), "l"(src));
}
#define CP_COMMIT() asm volatile("cp.async.commit_group;" ::: "memory")
#define CP_WAIT1()  asm volatile("cp.async.wait_group 1;" ::: "memory")

#define LDM_X4(r, a) asm volatile( \
    "ldmatrix.sync.aligned.m8n8.x4.shared.b16 {%0,%1,%2,%3}, [%4];" \
    : "=r"((r)[0]),"=r"((r)[1]),"=r"((r)[2]),"=r"((r)[3]) : "r"(a))

#define MMA_F16(c, a, b0v, b1v) asm volatile( \
    "mma.sync.aligned.m16n8k16.row.col.f32.f16.f16.f32 " \
    "{%0,%1,%2,%3},{%4,%5,%6,%7},{%8,%9},{%0,%1,%2,%3};" \
    : "+f"((c)[0]),"+f"((c)[1]),"+f"((c)[2]),"+f"((c)[3]) \
    : "r"((a)[0]),"r"((a)[1]),"r"((a)[2]),"r"((a)[3]), "r"(b0v),"r"(b1v))

// ---------------- mma.sync GEMM: CTA 128x256, warp 64x64, K-chunk 32, fp16 ----------------
// 3-stage cp.async pipeline, fp32 accumulate.
// MODE: 0 fp32 out; 2 fp16 row-major out; 3 fp16 transposed-per-batch out.
#define STG_A   0
#define STG_B   8192
#define STG_BYTES 24576
#define NSTG 3
#define TG_SMEM (NSTG * STG_BYTES)

template<int MODE, bool BIAS, bool RELU>
__global__ void __launch_bounds__(256, 1)
tgemm(const f16* __restrict__ Ah, const f16* __restrict__ Bh,
      float* __restrict__ Cf, f16* __restrict__ Ch,
      const float* __restrict__ bias,
      int K, int lda, int ldb, int ldc,
      long long sA, long long sB, long long cs1, long long cs2, int cdiv,
      float alpha)
{
    extern __shared__ __align__(16) char smem[];
    const u32 smb = smem_u32(smem);

    const int tid = threadIdx.x, lane = tid & 31, wid = tid >> 5;
    const int wm = wid >> 2, wn = wid & 3;                    // 2m x 4n warps, 64x64 each
    const int z = blockIdx.z, m0 = blockIdx.y * 128, n0 = blockIdx.x * 256;

    Ah += (long long)z * sA + (long long)m0 * lda;
    Bh += (long long)z * sB + (long long)n0 * ldb;
    const long long coff = (long long)(z / cdiv) * cs1 + (long long)(z % cdiv) * cs2;

    float acc[4][8][4];
    #pragma unroll
    for (int i = 0; i < 4; i++)
        #pragma unroll
        for (int j = 0; j < 8; j++)
            #pragma unroll
            for (int q = 0; q < 4; q++) acc[i][j][q] = 0.f;

    const int NT = K >> 5;

    #define ISSUE(cc) do { \
        const int kb = (cc) * 32; \
        const u32 stg_ = smb + (u32)((cc) % NSTG) * STG_BYTES; \
        _Pragma("unroll") \
        for (int t2 = 0; t2 < 2; t2++) { \
            const int task = t2 * 256 + tid; \
            const int row = task >> 2, seg = task & 3; \
            const u32 d_ = (u32)row * 64 + ((u32)(seg ^ ((row >> 1) & 3)) << 4); \
            cpa16(stg_ + STG_A + d_, Ah + (long long)row * lda + kb + seg * 8); \
        } \
        _Pragma("unroll") \
        for (int t4 = 0; t4 < 4; t4++) { \
            const int task = t4 * 256 + tid; \
            const int row = task >> 2, seg = task & 3; \
            const u32 d_ = (u32)row * 64 + ((u32)(seg ^ ((row >> 1) & 3)) << 4); \
            cpa16(stg_ + STG_B + d_, Bh + (long long)row * ldb + kb + seg * 8); \
        } \
        CP_COMMIT(); \
    } while (0)

    ISSUE(0);
    ISSUE(1);

    for (int c = 0; c < NT; c++) {
        CP_WAIT1();
        __syncthreads();
        const u32 stg = smb + (u32)(c % NSTG) * STG_BYTES;

        #pragma unroll
        for (int kk = 0; kk < 2; kk++) {
            u32 ah[4][4];
            const int arow = wm * 64 + (lane & 15);
            const int aks  = kk * 2 + (lane >> 4);
            #pragma unroll
            for (int mt = 0; mt < 4; mt++) {
                const int ro = arow + mt * 16;
                const u32 off = (u32)ro * 64 + ((u32)(aks ^ ((ro >> 1) & 3)) << 4);
                LDM_X4(ah[mt], stg + STG_A + off);
            }
            const int brow0 = wn * 64 + ((lane >> 4) & 1) * 8 + (lane & 7);
            const int bks = kk * 2 + ((lane >> 3) & 1);
            #pragma unroll
            for (int np = 0; np < 4; np++) {
                const int ro = brow0 + np * 16;
                const u32 off = (u32)ro * 64 + ((u32)(bks ^ ((ro >> 1) & 3)) << 4);
                u32 th[4];
                LDM_X4(th, stg + STG_B + off);
                #pragma unroll
                for (int mt = 0; mt < 4; mt++) {
                    MMA_F16(acc[mt][np*2],   ah[mt], th[0], th[1]);
                    MMA_F16(acc[mt][np*2+1], ah[mt], th[2], th[3]);
                }
            }
        }

        if (c + 2 < NT) { ISSUE(c + 2); } else { CP_COMMIT(); }
        __syncthreads();
    }
    #undef ISSUE

    // ---- epilogue: frag map rows lane>>2 (+8), cols (lane&3)*2 ----
    const int er = lane >> 2, ec = (lane & 3) * 2;
    #pragma unroll
    for (int mt = 0; mt < 4; mt++) {
        #pragma unroll
        for (int nt = 0; nt < 8; nt++) {
            const float* a4 = acc[mt][nt];
            const int row0 = m0 + wm * 64 + mt * 16 + er;
            const int col  = n0 + wn * 64 + nt * 8 + ec;
            float v00 = a4[0] * alpha, v01 = a4[1] * alpha;
            float v10 = a4[2] * alpha, v11 = a4[3] * alpha;
            if (BIAS) {
                const float bb0 = bias[col], bb1 = bias[col + 1];
                v00 += bb0; v01 += bb1; v10 += bb0; v11 += bb1;
            }
            if (RELU) {
                v00 = fmaxf(v00, 0.f); v01 = fmaxf(v01, 0.f);
                v10 = fmaxf(v10, 0.f); v11 = fmaxf(v11, 0.f);
            }
            if (MODE == 0) {
                float* C = Cf + coff;
                *(float2*)(C + (long long)row0 * ldc + col)       = make_float2(v00, v01);
                *(float2*)(C + (long long)(row0 + 8) * ldc + col) = make_float2(v10, v11);
            } else if (MODE == 2) {
                __half2 p0, p1;
                p0.x = __float2half(v00); p0.y = __float2half(v01);
                p1.x = __float2half(v10); p1.y = __float2half(v11);
                *(__half2*)(Ch + coff + (long long)row0 * ldc + col)       = p0;
                *(__half2*)(Ch + coff + (long long)(row0 + 8) * ldc + col) = p1;
            } else {
                // transposed: addr(e, token) = coff + (tok>>11)*(CD*CS) + (tok&2047) + e*CS
                const long long o0 = coff + (long long)(row0 >> 11) * ((long long)CD * CS) + (row0 & (CS - 1));
                const int r1 = row0 + 8;
                const long long o1 = coff + (long long)(r1 >> 11) * ((long long)CD * CS) + (r1 & (CS - 1));
                Ch[o0 + (long long)col * CS]       = __float2half(v00);
                Ch[o0 + (long long)(col + 1) * CS] = __float2half(v01);
                Ch[o1 + (long long)col * CS]       = __float2half(v10);
                Ch[o1 + (long long)(col + 1) * CS] = __float2half(v11);
            }
        }
    }
}

// ---------------- fp32 -> fp16 ----------------
__global__ void __launch_bounds__(256)
conv1_k(const float* __restrict__ in, f16* __restrict__ oh){
    const long long i = (long long)blockIdx.x * 256 + threadIdx.x;
    oh[i] = __float2half(in[i]);
}

// ---------------- fp32 [R,C] -> fp16 [C,R] (batched) ----------------
__global__ void __launch_bounds__(256)
transp_pack_k(const float* __restrict__ in, f16* __restrict__ oh,
              int R, int Cc, long long sIn, long long sOut){
    __shared__ float sm[32][33];
    const float* ip = in + (long long)blockIdx.z * sIn;
    f16* oph = oh + (long long)blockIdx.z * sOut;
    const int x0 = blockIdx.x * 32, y0 = blockIdx.y * 32;
    const int tx = threadIdx.x & 31, ty = threadIdx.x >> 5;
    #pragma unroll
    for (int j = 0; j < 32; j += 8)
        sm[ty + j][tx] = ip[(long long)(y0 + ty + j) * Cc + x0 + tx];
    __syncthreads();
    #pragma unroll
    for (int j = 0; j < 32; j += 8)
        oph[(long long)(x0 + ty + j) * R + y0 + tx] = __float2half(sm[tx][ty + j]);
}

// ---------------- softmax row 2048: f16 in -> f16 out ----------------
__global__ void __launch_bounds__(256)
softmax_k(const f16* __restrict__ sc, f16* __restrict__ oh){
    const long long row = blockIdx.x;
    const f16* p = sc + row * (long long)CS;
    f16* o = oh + row * (long long)CS;
    const int tid = threadIdx.x;
    __shared__ float sm[8];
    float v[8], mx = -3.4e38f;
    #pragma unroll
    for (int i = 0; i < 8; i++){ v[i] = __half2float(p[tid + i*256]); mx = fmaxf(mx, v[i]); }
    #pragma unroll
    for (int w = 16; w; w >>= 1) mx = fmaxf(mx, __shfl_xor_sync(~0u, mx, w));
    if ((tid & 31) == 0) sm[tid >> 5] = mx;
    __syncthreads();
    if (tid < 32){
        float t = (tid < 8) ? sm[tid] : -3.4e38f;
        #pragma unroll
        for (int w = 4; w; w >>= 1) t = fmaxf(t, __shfl_xor_sync(~0u, t, w));
        if (tid == 0) sm[0] = t;
    }
    __syncthreads(); mx = sm[0]; __syncthreads();
    float s = 0.f;
    #pragma unroll
    for (int i = 0; i < 8; i++){ v[i] = __expf(v[i] - mx); s += v[i]; }
    #pragma unroll
    for (int w = 16; w; w >>= 1) s += __shfl_xor_sync(~0u, s, w);
    if ((tid & 31) == 0) sm[tid >> 5] = s;
    __syncthreads();
    if (tid < 32){
        float t = (tid < 8) ? sm[tid] : 0.f;
        #pragma unroll
        for (int w = 4; w; w >>= 1) t += __shfl_xor_sync(~0u, t, w);
        if (tid == 0) sm[0] = t;
    }
    __syncthreads();
    const float inv = 1.0f / sm[0];
    #pragma unroll
    for (int i = 0; i < 8; i++) o[tid + i*256] = __float2half(v[i] * inv);
}

// ---------------- out = LN(x+y)*g+b (+fp16 copy) ----------------
template<bool PK>
__global__ void __launch_bounds__(256)
add_ln_k(const float* __restrict__ x, const float* __restrict__ y,
         const float* __restrict__ g, const float* __restrict__ b,
         float* __restrict__ out, f16* __restrict__ oh){
    const long long row = blockIdx.x;
    const float* px = x + row * (long long)CD;
    const float* py = y + row * (long long)CD;
    float* po = out + row * (long long)CD;
    const int tid = threadIdx.x;
    __shared__ float sm[16];
    float v[4], s = 0.f, s2 = 0.f;
    #pragma unroll
    for (int i = 0; i < 4; i++){
        float t = px[tid + i*256] + py[tid + i*256];
        v[i] = t; s += t; s2 += t*t;
    }
    #pragma unroll
    for (int w = 16; w; w >>= 1){ s += __shfl_xor_sync(~0u, s, w); s2 += __shfl_xor_sync(~0u, s2, w); }
    if ((tid & 31) == 0){ sm[tid>>5] = s; sm[8 + (tid>>5)] = s2; }
    __syncthreads();
    if (tid < 32){
        float t = (tid < 8) ? sm[tid] : 0.f, t2 = (tid < 8) ? sm[8+tid] : 0.f;
        #pragma unroll
        for (int w = 4; w; w >>= 1){ t += __shfl_xor_sync(~0u, t, w); t2 += __shfl_xor_sync(~0u, t2, w); }
        if (tid == 0){ sm[0] = t; sm[8] = t2; }
    }
    __syncthreads();
    const float mean = sm[0] * (1.0f/CD);
    const float var  = sm[8] * (1.0f/CD) - mean*mean;
    const float rs = rsqrtf(var + 1e-5f);
    #pragma unroll
    for (int i = 0; i < 4; i++){
        const int c = tid + i*256;
        const float o = (v[i] - mean) * rs * g[c] + b[c];
        po[c] = o;
        if (PK) oh[row * (long long)CD + c] = __float2half(o);
    }
}

// ---------------- kernel_launch ----------------
extern "C" void kernel_launch(void* const* d_in, const int* in_sizes, int n_in,
                              void* d_out, int out_size)
{
    const float* x  = (const float*)d_in[0];
    const float* Wq = (const float*)d_in[1];
    const float* Wk = (const float*)d_in[2];
    const float* Wv = (const float*)d_in[3];
    const float* Wo = (const float*)d_in[4];
    const float* bo = (const float*)d_in[5];
    const float* w1 = (const float*)d_in[6];
    const float* b1 = (const float*)d_in[7];
    const float* w2 = (const float*)d_in[8];
    const float* b2 = (const float*)d_in[9];
    const float* w3 = (const float*)d_in[10];
    const float* b3 = (const float*)d_in[11];
    const float* w4 = (const float*)d_in[12];
    const float* b4 = (const float*)d_in[13];
    const float* g1 = (const float*)d_in[14];
    const float* be1= (const float*)d_in[15];
    const float* g2 = (const float*)d_in[16];
    const float* be2= (const float*)d_in[17];
    float* out = (float*)d_out;

    f16 *Xh,*Wqh,*Wkh,*Wvh,*Woh,*W1h,*W2h,*W3h,*W4h;
    f16 *Qh,*Kh,*VTh,*SCb,*ATh,*ZCh,*Y1h,*Y2h,*ZNh;
    float *AO,*Z1;
    cudaGetSymbolAddress((void**)&Xh,  g_X_h_);
    cudaGetSymbolAddress((void**)&Wqh, g_Wq_h_);
    cudaGetSymbolAddress((void**)&Wkh, g_Wk_h_);
    cudaGetSymbolAddress((void**)&Wvh, g_Wv_h_);
    cudaGetSymbolAddress((void**)&Woh, g_Wo_h_);
    cudaGetSymbolAddress((void**)&W1h, g_W1_h_);
    cudaGetSymbolAddress((void**)&W2h, g_W2_h_);
    cudaGetSymbolAddress((void**)&W3h, g_W3_h_);
    cudaGetSymbolAddress((void**)&W4h, g_W4_h_);
    cudaGetSymbolAddress((void**)&Qh,  g_Q_h_);
    cudaGetSymbolAddress((void**)&Kh,  g_K_h_);
    cudaGetSymbolAddress((void**)&VTh, g_VT_h_);
    cudaGetSymbolAddress((void**)&SCb, g_SCb_h_);
    cudaGetSymbolAddress((void**)&ATh, g_AT_h_);
    cudaGetSymbolAddress((void**)&ZCh, g_ZC_h_);
    cudaGetSymbolAddress((void**)&Y1h, g_Y1_h_);
    cudaGetSymbolAddress((void**)&Y2h, g_Y2_h_);
    cudaGetSymbolAddress((void**)&ZNh, g_ZN_h_);
    cudaGetSymbolAddress((void**)&AO, g_AO);
    cudaGetSymbolAddress((void**)&Z1, g_Z1);

    cudaFuncSetAttribute(tgemm<2,false,false>, cudaFuncAttributeMaxDynamicSharedMemorySize, TG_SMEM);
    cudaFuncSetAttribute(tgemm<3,false,false>, cudaFuncAttributeMaxDynamicSharedMemorySize, TG_SMEM);
    cudaFuncSetAttribute(tgemm<0,true,false>,  cudaFuncAttributeMaxDynamicSharedMemorySize, TG_SMEM);
    cudaFuncSetAttribute(tgemm<2,true,true>,   cudaFuncAttributeMaxDynamicSharedMemorySize, TG_SMEM);

    const int MT = CB * CS;                       // 8192
    const long long DD  = (long long)CD * CD;
    const long long HBD = (long long)CB * CS * CD;
    const long long SD  = (long long)CS * CD;
    const long long SS  = (long long)CS * CS;

    // ---- prep ----
    conv1_k<<<MT * CD / 256, 256>>>(x, Xh);
    transp_pack_k<<<dim3(32, 32, CH), 256>>>(Wq, Wqh, CD, CD, DD, DD);
    transp_pack_k<<<dim3(32, 32, CH), 256>>>(Wk, Wkh, CD, CD, DD, DD);
    transp_pack_k<<<dim3(32, 32, CH), 256>>>(Wv, Wvh, CD, CD, DD, DD);
    transp_pack_k<<<dim3(32, 256, 1), 256>>>(Wo, Woh, CH * CD, CD, 0, 0);
    transp_pack_k<<<dim3(128, 32, 1), 256>>>(w1, W1h, CD, CHID, 0, 0);
    transp_pack_k<<<dim3(128, 128, 1), 256>>>(w2, W2h, CHID, CHID, 0, 0);
    transp_pack_k<<<dim3(128, 128, 1), 256>>>(w3, W3h, CHID, CHID, 0, 0);
    transp_pack_k<<<dim3(32, 128, 1), 256>>>(w4, W4h, CHID, CD, 0, 0);

    // ---- QKV ----
    {
        dim3 grid(CD / 256, MT / 128, CH);
        tgemm<2,false,false><<<grid, 256, TG_SMEM>>>(Xh, Wqh,
            nullptr, Qh, nullptr, CD, CD, CD, CD, 0, DD, HBD, 0, 1, 1.0f);
        tgemm<2,false,false><<<grid, 256, TG_SMEM>>>(Xh, Wkh,
            nullptr, Kh, nullptr, CD, CD, CD, CD, 0, DD, HBD, 0, 1, 1.0f);
        tgemm<3,false,false><<<grid, 256, TG_SMEM>>>(Xh, Wvh,
            nullptr, VTh, nullptr, CD, CD, CD, 0, 0, DD, HBD, 0, 1, 1.0f);
    }
    // ---- scores = Q K^T / 32 ----
    {
        dim3 grid(CS / 256, CS / 128, CH * CB);
        tgemm<2,false,false><<<grid, 256, TG_SMEM>>>(Qh, Kh,
            nullptr, SCb, nullptr, CD, CD, CD, CS, SD, SD, SS, 0, 1, 0.03125f);
    }
    // ---- softmax ----
    softmax_k<<<CH * CB * CS, 256>>>(SCb, ATh);
    // ---- Z = attn @ V -> head-concat ----
    {
        dim3 grid(CD / 256, CS / 128, CH * CB);
        tgemm<2,false,false><<<grid, 256, TG_SMEM>>>(ATh, VTh,
            nullptr, ZCh, nullptr, CS, CS, CS, CH * CD, SS, (long long)CD * CS,
            (long long)CD, (long long)CS * CH * CD, CB, 1.0f);
    }
    // ---- attn_out = ZC @ Wo + bo ----
    {
        dim3 grid(CD / 256, MT / 128, 1);
        tgemm<0,true,false><<<grid, 256, TG_SMEM>>>(ZCh, Woh,
            AO, nullptr, bo, CH * CD, CH * CD, CH * CD, CD, 0, 0, 0, 0, 1, 1.0f);
    }
    // ---- Z1 = LN(x + attn_out) ----
    add_ln_k<true><<<MT, 256>>>(x, AO, g1, be1, Z1, ZNh);
    // ---- FFN ----
    {
        dim3 gh(CHID / 256, MT / 128, 1);
        tgemm<2,true,true><<<gh, 256, TG_SMEM>>>(ZNh, W1h,
            nullptr, Y1h, b1, CD, CD, CD, CHID, 0, 0, 0, 0, 1, 1.0f);
        tgemm<2,true,true><<<gh, 256, TG_SMEM>>>(Y1h, W2h,
            nullptr, Y2h, b2, CHID, CHID, CHID, CHID, 0, 0, 0, 0, 1, 1.0f);
        tgemm<2,true,true><<<gh, 256, TG_SMEM>>>(Y2h, W3h,
            nullptr, Y1h, b3, CHID, CHID, CHID, CHID, 0, 0, 0, 0, 1, 1.0f);
        dim3 g4(CD / 256, MT / 128, 1);
        tgemm<0,true,false><<<g4, 256, TG_SMEM>>>(Y1h, W4h,
            AO, nullptr, b4, CHID, CHID, CHID, CD, 0, 0, 0, 0, 1, 1.0f);
    }
    // ---- out = LN(Z1 + ffn_out) ----
    add_ln_k<false><<<MT, 256>>>(Z1, AO, g2, be2, out, nullptr);
}

// round 15
// speedup vs baseline: 1.3304x; 1.3304x over previous
#include <cuda_runtime.h>
#include <cuda_fp16.h>
#include <math.h>

typedef unsigned int u32;
typedef unsigned long long u64;
typedef __half f16;

#define CB 4
#define CS 2048
#define CD 1024
#define CH 8
#define CHID 4096

// ---------------- scratch (device globals) ----------------
#define DECL_ONE(name, n) __device__ uint4 name##_h_[(size_t)(n) / 8];

DECL_ONE(g_X,  (size_t)CB*CS*CD)
DECL_ONE(g_Wq, (size_t)CH*CD*CD)
DECL_ONE(g_Wk, (size_t)CH*CD*CD)
DECL_ONE(g_Wv, (size_t)CH*CD*CD)
DECL_ONE(g_Wo, (size_t)CD*CH*CD)
DECL_ONE(g_W1, (size_t)CHID*CD)
DECL_ONE(g_W2, (size_t)CHID*CHID)
DECL_ONE(g_W3, (size_t)CHID*CHID)
DECL_ONE(g_W4, (size_t)CD*CHID)
DECL_ONE(g_Q,  (size_t)CH*CB*CS*CD)     // [(h,b)][s][d]
DECL_ONE(g_K,  (size_t)CH*CB*CS*CD)
DECL_ONE(g_VT, (size_t)CH*CB*CD*CS)     // [h][b][e][t]
DECL_ONE(g_SCb,(size_t)CH*CB*CS*CS)     // scores f16
DECL_ONE(g_AT, (size_t)CH*CB*CS*CS)     // attn f16
DECL_ONE(g_ZC, (size_t)CB*CS*CH*CD)     // head-concat f16
DECL_ONE(g_Y1, (size_t)CB*CS*CHID)
DECL_ONE(g_Y2, (size_t)CB*CS*CHID)
DECL_ONE(g_ZN, (size_t)CB*CS*CD)
__device__ float g_AO[(size_t)CB*CS*CD];
__device__ float g_Z1[(size_t)CB*CS*CD];

// ---------------- helpers ----------------
__device__ __forceinline__ u32 smem_u32(const void* p){
    u32 a; asm("{ .reg .u64 t; cvta.to.shared.u64 t, %1; cvt.u32.u64 %0, t; }":"=r"(a):"l"(p)); return a;
}
__device__ __forceinline__ void cpa16(u32 dst, const void* src){
    asm volatile("cp.async.cg.shared.global [%0], [%1], 16;" :: "r"(dst), "l"(src));
}
#define CP_COMMIT() asm volatile("cp.async.commit_group;" ::: "memory")
#define CP_WAIT1()  asm volatile("cp.async.wait_group 1;" ::: "memory")

#define LDM_X4(r, a) asm volatile( \
    "ldmatrix.sync.aligned.m8n8.x4.shared.b16 {%0,%1,%2,%3}, [%4];" \
    : "=r"((r)[0]),"=r"((r)[1]),"=r"((r)[2]),"=r"((r)[3]) : "r"(a))

#define MMA_F16(c, a, b0v, b1v) asm volatile( \
    "mma.sync.aligned.m16n8k16.row.col.f32.f16.f16.f32 " \
    "{%0,%1,%2,%3},{%4,%5,%6,%7},{%8,%9},{%0,%1,%2,%3};" \
    : "+f"((c)[0]),"+f"((c)[1]),"+f"((c)[2]),"+f"((c)[3]) \
    : "r"((a)[0]),"r"((a)[1]),"r"((a)[2]),"r"((a)[3]), "r"(b0v),"r"(b1v))

// ---------------- mma.sync GEMM: CTA 128x256, warp 64x64, K-chunk 32, fp16 ----------------
// 3-stage cp.async pipeline, fp32 accumulate, per-chunk fragment double-buffer.
// MODE: 0 fp32 out; 2 fp16 row-major out; 3 fp16 transposed-per-batch out.
#define STG_A   0
#define STG_B   8192
#define STG_BYTES 24576
#define NSTG 3
#define TG_SMEM (NSTG * STG_BYTES)

template<int MODE, bool BIAS, bool RELU>
__global__ void __launch_bounds__(256, 1)
tgemm(const f16* __restrict__ Ah, const f16* __restrict__ Bh,
      float* __restrict__ Cf, f16* __restrict__ Ch,
      const float* __restrict__ bias,
      int K, int lda, int ldb, int ldc,
      long long sA, long long sB, long long cs1, long long cs2, int cdiv,
      float alpha)
{
    extern __shared__ __align__(16) char smem[];
    const u32 smb = smem_u32(smem);

    const int tid = threadIdx.x, lane = tid & 31, wid = tid >> 5;
    const int wm = wid >> 2, wn = wid & 3;                    // 2m x 4n warps, 64x64 each
    const int z = blockIdx.z, m0 = blockIdx.y * 128, n0 = blockIdx.x * 256;

    Ah += (long long)z * sA + (long long)m0 * lda;
    Bh += (long long)z * sB + (long long)n0 * ldb;
    const long long coff = (long long)(z / cdiv) * cs1 + (long long)(z % cdiv) * cs2;

    float acc[4][8][4];
    #pragma unroll
    for (int i = 0; i < 4; i++)
        #pragma unroll
        for (int j = 0; j < 8; j++)
            #pragma unroll
            for (int q = 0; q < 4; q++) acc[i][j][q] = 0.f;

    const int NT = K >> 5;

    // precomputed fragment row indices
    const int arow = wm * 64 + (lane & 15);
    const int aseg = lane >> 4;                   // 0/1
    const int brow0 = wn * 64 + ((lane >> 4) & 1) * 8 + (lane & 7);
    const int bseg = (lane >> 3) & 1;

    #define LOAD_FRAGS(kk, FA, FB, stg) do { \
        const int aks_ = (kk) * 2 + aseg; \
        _Pragma("unroll") \
        for (int mt = 0; mt < 4; mt++) { \
            const int ro = arow + mt * 16; \
            const u32 off = (u32)ro * 64 + ((u32)(aks_ ^ ((ro >> 1) & 3)) << 4); \
            LDM_X4(FA[mt], (stg) + STG_A + off); \
        } \
        const int bks_ = (kk) * 2 + bseg; \
        _Pragma("unroll") \
        for (int np = 0; np < 4; np++) { \
            const int ro = brow0 + np * 16; \
            const u32 off = (u32)ro * 64 + ((u32)(bks_ ^ ((ro >> 1) & 3)) << 4); \
            LDM_X4(FB[np], (stg) + STG_B + off); \
        } \
    } while (0)

    #define MMA_SET(FA, FB) do { \
        _Pragma("unroll") \
        for (int np = 0; np < 4; np++) \
            _Pragma("unroll") \
            for (int mt = 0; mt < 4; mt++) { \
                MMA_F16(acc[mt][np*2],   FA[mt], FB[np][0], FB[np][1]); \
                MMA_F16(acc[mt][np*2+1], FA[mt], FB[np][2], FB[np][3]); \
            } \
    } while (0)

    #define ISSUE(cc) do { \
        const int kb = (cc) * 32; \
        const u32 stg_ = smb + (u32)((cc) % NSTG) * STG_BYTES; \
        _Pragma("unroll") \
        for (int t2 = 0; t2 < 2; t2++) { \
            const int task = t2 * 256 + tid; \
            const int row = task >> 2, seg = task & 3; \
            const u32 d_ = (u32)row * 64 + ((u32)(seg ^ ((row >> 1) & 3)) << 4); \
            cpa16(stg_ + STG_A + d_, Ah + (long long)row * lda + kb + seg * 8); \
        } \
        _Pragma("unroll") \
        for (int t4 = 0; t4 < 4; t4++) { \
            const int task = t4 * 256 + tid; \
            const int row = task >> 2, seg = task & 3; \
            const u32 d_ = (u32)row * 64 + ((u32)(seg ^ ((row >> 1) & 3)) << 4); \
            cpa16(stg_ + STG_B + d_, Bh + (long long)row * ldb + kb + seg * 8); \
        } \
        CP_COMMIT(); \
    } while (0)

    ISSUE(0);
    ISSUE(1);

    for (int c = 0; c < NT; c++) {
        CP_WAIT1();
        __syncthreads();
        const u32 stg = smb + (u32)(c % NSTG) * STG_BYTES;

        u32 fa0[4][4], fb0[4][4], fa1[4][4], fb1[4][4];
        LOAD_FRAGS(0, fa0, fb0, stg);
        LOAD_FRAGS(1, fa1, fb1, stg);
        if (c + 2 < NT) { ISSUE(c + 2); } else { CP_COMMIT(); }
        MMA_SET(fa0, fb0);
        MMA_SET(fa1, fb1);
        __syncthreads();
    }
    #undef ISSUE
    #undef LOAD_FRAGS
    #undef MMA_SET

    // ---- epilogue: frag map rows lane>>2 (+8), cols (lane&3)*2 ----
    const int er = lane >> 2, ec = (lane & 3) * 2;
    #pragma unroll
    for (int mt = 0; mt < 4; mt++) {
        #pragma unroll
        for (int nt = 0; nt < 8; nt++) {
            const float* a4 = acc[mt][nt];
            const int row0 = m0 + wm * 64 + mt * 16 + er;
            const int col  = n0 + wn * 64 + nt * 8 + ec;
            float v00 = a4[0] * alpha, v01 = a4[1] * alpha;
            float v10 = a4[2] * alpha, v11 = a4[3] * alpha;
            if (BIAS) {
                const float bb0 = bias[col], bb1 = bias[col + 1];
                v00 += bb0; v01 += bb1; v10 += bb0; v11 += bb1;
            }
            if (RELU) {
                v00 = fmaxf(v00, 0.f); v01 = fmaxf(v01, 0.f);
                v10 = fmaxf(v10, 0.f); v11 = fmaxf(v11, 0.f);
            }
            if (MODE == 0) {
                float* C = Cf + coff;
                *(float2*)(C + (long long)row0 * ldc + col)       = make_float2(v00, v01);
                *(float2*)(C + (long long)(row0 + 8) * ldc + col) = make_float2(v10, v11);
            } else if (MODE == 2) {
                __half2 p0, p1;
                p0.x = __float2half(v00); p0.y = __float2half(v01);
                p1.x = __float2half(v10); p1.y = __float2half(v11);
                *(__half2*)(Ch + coff + (long long)row0 * ldc + col)       = p0;
                *(__half2*)(Ch + coff + (long long)(row0 + 8) * ldc + col) = p1;
            } else {
                const long long o0 = coff + (long long)(row0 >> 11) * ((long long)CD * CS) + (row0 & (CS - 1));
                const int r1 = row0 + 8;
                const long long o1 = coff + (long long)(r1 >> 11) * ((long long)CD * CS) + (r1 & (CS - 1));
                Ch[o0 + (long long)col * CS]       = __float2half(v00);
                Ch[o0 + (long long)(col + 1) * CS] = __float2half(v01);
                Ch[o1 + (long long)col * CS]       = __float2half(v10);
                Ch[o1 + (long long)(col + 1) * CS] = __float2half(v11);
            }
        }
    }
}

// ---------------- fp32 -> fp16 ----------------
__global__ void __launch_bounds__(256)
conv1_k(const float* __restrict__ in, f16* __restrict__ oh){
    const long long i = (long long)blockIdx.x * 256 + threadIdx.x;
    oh[i] = __float2half(in[i]);
}

// ---------------- fp32 [R,C] -> fp16 [C,R] (batched) ----------------
__global__ void __launch_bounds__(256)
transp_pack_k(const float* __restrict__ in, f16* __restrict__ oh,
              int R, int Cc, long long sIn, long long sOut){
    __shared__ float sm[32][33];
    const float* ip = in + (long long)blockIdx.z * sIn;
    f16* oph = oh + (long long)blockIdx.z * sOut;
    const int x0 = blockIdx.x * 32, y0 = blockIdx.y * 32;
    const int tx = threadIdx.x & 31, ty = threadIdx.x >> 5;
    #pragma unroll
    for (int j = 0; j < 32; j += 8)
        sm[ty + j][tx] = ip[(long long)(y0 + ty + j) * Cc + x0 + tx];
    __syncthreads();
    #pragma unroll
    for (int j = 0; j < 32; j += 8)
        oph[(long long)(x0 + ty + j) * R + y0 + tx] = __float2half(sm[tx][ty + j]);
}

// ---------------- softmax row 2048: f16 in -> f16 out ----------------
__global__ void __launch_bounds__(256)
softmax_k(const f16* __restrict__ sc, f16* __restrict__ oh){
    const long long row = blockIdx.x;
    const f16* p = sc + row * (long long)CS;
    f16* o = oh + row * (long long)CS;
    const int tid = threadIdx.x;
    __shared__ float sm[8];
    float v[8], mx = -3.4e38f;
    #pragma unroll
    for (int i = 0; i < 8; i++){ v[i] = __half2float(p[tid + i*256]); mx = fmaxf(mx, v[i]); }
    #pragma unroll
    for (int w = 16; w; w >>= 1) mx = fmaxf(mx, __shfl_xor_sync(~0u, mx, w));
    if ((tid & 31) == 0) sm[tid >> 5] = mx;
    __syncthreads();
    if (tid < 32){
        float t = (tid < 8) ? sm[tid] : -3.4e38f;
        #pragma unroll
        for (int w = 4; w; w >>= 1) t = fmaxf(t, __shfl_xor_sync(~0u, t, w));
        if (tid == 0) sm[0] = t;
    }
    __syncthreads(); mx = sm[0]; __syncthreads();
    float s = 0.f;
    #pragma unroll
    for (int i = 0; i < 8; i++){ v[i] = __expf(v[i] - mx); s += v[i]; }
    #pragma unroll
    for (int w = 16; w; w >>= 1) s += __shfl_xor_sync(~0u, s, w);
    if ((tid & 31) == 0) sm[tid >> 5] = s;
    __syncthreads();
    if (tid < 32){
        float t = (tid < 8) ? sm[tid] : 0.f;
        #pragma unroll
        for (int w = 4; w; w >>= 1) t += __shfl_xor_sync(~0u, t, w);
        if (tid == 0) sm[0] = t;
    }
    __syncthreads();
    const float inv = 1.0f / sm[0];
    #pragma unroll
    for (int i = 0; i < 8; i++) o[tid + i*256] = __float2half(v[i] * inv);
}

// ---------------- out = LN(x+y)*g+b (+fp16 copy) ----------------
template<bool PK>
__global__ void __launch_bounds__(256)
add_ln_k(const float* __restrict__ x, const float* __restrict__ y,
         const float* __restrict__ g, const float* __restrict__ b,
         float* __restrict__ out, f16* __restrict__ oh){
    const long long row = blockIdx.x;
    const float* px = x + row * (long long)CD;
    const float* py = y + row * (long long)CD;
    float* po = out + row * (long long)CD;
    const int tid = threadIdx.x;
    __shared__ float sm[16];
    float v[4], s = 0.f, s2 = 0.f;
    #pragma unroll
    for (int i = 0; i < 4; i++){
        float t = px[tid + i*256] + py[tid + i*256];
        v[i] = t; s += t; s2 += t*t;
    }
    #pragma unroll
    for (int w = 16; w; w >>= 1){ s += __shfl_xor_sync(~0u, s, w); s2 += __shfl_xor_sync(~0u, s2, w); }
    if ((tid & 31) == 0){ sm[tid>>5] = s; sm[8 + (tid>>5)] = s2; }
    __syncthreads();
    if (tid < 32){
        float t = (tid < 8) ? sm[tid] : 0.f, t2 = (tid < 8) ? sm[8+tid] : 0.f;
        #pragma unroll
        for (int w = 4; w; w >>= 1){ t += __shfl_xor_sync(~0u, t, w); t2 += __shfl_xor_sync(~0u, t2, w); }
        if (tid == 0){ sm[0] = t; sm[8] = t2; }
    }
    __syncthreads();
    const float mean = sm[0] * (1.0f/CD);
    const float var  = sm[8] * (1.0f/CD) - mean*mean;
    const float rs = rsqrtf(var + 1e-5f);
    #pragma unroll
    for (int i = 0; i < 4; i++){
        const int c = tid + i*256;
        const float o = (v[i] - mean) * rs * g[c] + b[c];
        po[c] = o;
        if (PK) oh[row * (long long)CD + c] = __float2half(o);
    }
}

// ---------------- kernel_launch ----------------
extern "C" void kernel_launch(void* const* d_in, const int* in_sizes, int n_in,
                              void* d_out, int out_size)
{
    const float* x  = (const float*)d_in[0];
    const float* Wq = (const float*)d_in[1];
    const float* Wk = (const float*)d_in[2];
    const float* Wv = (const float*)d_in[3];
    const float* Wo = (const float*)d_in[4];
    const float* bo = (const float*)d_in[5];
    const float* w1 = (const float*)d_in[6];
    const float* b1 = (const float*)d_in[7];
    const float* w2 = (const float*)d_in[8];
    const float* b2 = (const float*)d_in[9];
    const float* w3 = (const float*)d_in[10];
    const float* b3 = (const float*)d_in[11];
    const float* w4 = (const float*)d_in[12];
    const float* b4 = (const float*)d_in[13];
    const float* g1 = (const float*)d_in[14];
    const float* be1= (const float*)d_in[15];
    const float* g2 = (const float*)d_in[16];
    const float* be2= (const float*)d_in[17];
    float* out = (float*)d_out;

    f16 *Xh,*Wqh,*Wkh,*Wvh,*Woh,*W1h,*W2h,*W3h,*W4h;
    f16 *Qh,*Kh,*VTh,*SCb,*ATh,*ZCh,*Y1h,*Y2h,*ZNh;
    float *AO,*Z1;
    cudaGetSymbolAddress((void**)&Xh,  g_X_h_);
    cudaGetSymbolAddress((void**)&Wqh, g_Wq_h_);
    cudaGetSymbolAddress((void**)&Wkh, g_Wk_h_);
    cudaGetSymbolAddress((void**)&Wvh, g_Wv_h_);
    cudaGetSymbolAddress((void**)&Woh, g_Wo_h_);
    cudaGetSymbolAddress((void**)&W1h, g_W1_h_);
    cudaGetSymbolAddress((void**)&W2h, g_W2_h_);
    cudaGetSymbolAddress((void**)&W3h, g_W3_h_);
    cudaGetSymbolAddress((void**)&W4h, g_W4_h_);
    cudaGetSymbolAddress((void**)&Qh,  g_Q_h_);
    cudaGetSymbolAddress((void**)&Kh,  g_K_h_);
    cudaGetSymbolAddress((void**)&VTh, g_VT_h_);
    cudaGetSymbolAddress((void**)&SCb, g_SCb_h_);
    cudaGetSymbolAddress((void**)&ATh, g_AT_h_);
    cudaGetSymbolAddress((void**)&ZCh, g_ZC_h_);
    cudaGetSymbolAddress((void**)&Y1h, g_Y1_h_);
    cudaGetSymbolAddress((void**)&Y2h, g_Y2_h_);
    cudaGetSymbolAddress((void**)&ZNh, g_ZN_h_);
    cudaGetSymbolAddress((void**)&AO, g_AO);
    cudaGetSymbolAddress((void**)&Z1, g_Z1);

    cudaFuncSetAttribute(tgemm<2,false,false>, cudaFuncAttributeMaxDynamicSharedMemorySize, TG_SMEM);
    cudaFuncSetAttribute(tgemm<3,false,false>, cudaFuncAttributeMaxDynamicSharedMemorySize, TG_SMEM);
    cudaFuncSetAttribute(tgemm<0,true,false>,  cudaFuncAttributeMaxDynamicSharedMemorySize, TG_SMEM);
    cudaFuncSetAttribute(tgemm<2,true,true>,   cudaFuncAttributeMaxDynamicSharedMemorySize, TG_SMEM);

    const int MT = CB * CS;                       // 8192
    const long long DD  = (long long)CD * CD;
    const long long HBD = (long long)CB * CS * CD;
    const long long SD  = (long long)CS * CD;
    const long long SS  = (long long)CS * CS;

    // ---- prep ----
    conv1_k<<<MT * CD / 256, 256>>>(x, Xh);
    transp_pack_k<<<dim3(32, 32, CH), 256>>>(Wq, Wqh, CD, CD, DD, DD);
    transp_pack_k<<<dim3(32, 32, CH), 256>>>(Wk, Wkh, CD, CD, DD, DD);
    transp_pack_k<<<dim3(32, 32, CH), 256>>>(Wv, Wvh, CD, CD, DD, DD);
    transp_pack_k<<<dim3(32, 256, 1), 256>>>(Wo, Woh, CH * CD, CD, 0, 0);
    transp_pack_k<<<dim3(128, 32, 1), 256>>>(w1, W1h, CD, CHID, 0, 0);
    transp_pack_k<<<dim3(128, 128, 1), 256>>>(w2, W2h, CHID, CHID, 0, 0);
    transp_pack_k<<<dim3(128, 128, 1), 256>>>(w3, W3h, CHID, CHID, 0, 0);
    transp_pack_k<<<dim3(32, 128, 1), 256>>>(w4, W4h, CHID, CD, 0, 0);

    // ---- QKV ----
    {
        dim3 grid(CD / 256, MT / 128, CH);
        tgemm<2,false,false><<<grid, 256, TG_SMEM>>>(Xh, Wqh,
            nullptr, Qh, nullptr, CD, CD, CD, CD, 0, DD, HBD, 0, 1, 1.0f);
        tgemm<2,false,false><<<grid, 256, TG_SMEM>>>(Xh, Wkh,
            nullptr, Kh, nullptr, CD, CD, CD, CD, 0, DD, HBD, 0, 1, 1.0f);
        tgemm<3,false,false><<<grid, 256, TG_SMEM>>>(Xh, Wvh,
            nullptr, VTh, nullptr, CD, CD, CD, 0, 0, DD, HBD, 0, 1, 1.0f);
    }
    // ---- scores = Q K^T / 32 ----
    {
        dim3 grid(CS / 256, CS / 128, CH * CB);
        tgemm<2,false,false><<<grid, 256, TG_SMEM>>>(Qh, Kh,
            nullptr, SCb, nullptr, CD, CD, CD, CS, SD, SD, SS, 0, 1, 0.03125f);
    }
    // ---- softmax ----
    softmax_k<<<CH * CB * CS, 256>>>(SCb, ATh);
    // ---- Z = attn @ V -> head-concat ----
    {
        dim3 grid(CD / 256, CS / 128, CH * CB);
        tgemm<2,false,false><<<grid, 256, TG_SMEM>>>(ATh, VTh,
            nullptr, ZCh, nullptr, CS, CS, CS, CH * CD, SS, (long long)CD * CS,
            (long long)CD, (long long)CS * CH * CD, CB, 1.0f);
    }
    // ---- attn_out = ZC @ Wo + bo ----
    {
        dim3 grid(CD / 256, MT / 128, 1);
        tgemm<0,true,false><<<grid, 256, TG_SMEM>>>(ZCh, Woh,
            AO, nullptr, bo, CH * CD, CH * CD, CH * CD, CD, 0, 0, 0, 0, 1, 1.0f);
    }
    // ---- Z1 = LN(x + attn_out) ----
    add_ln_k<true><<<MT, 256>>>(x, AO, g1, be1, Z1, ZNh);
    // ---- FFN ----
    {
        dim3 gh(CHID / 256, MT / 128, 1);
        tgemm<2,true,true><<<gh, 256, TG_SMEM>>>(ZNh, W1h,
            nullptr, Y1h, b1, CD, CD, CD, CHID, 0, 0, 0, 0, 1, 1.0f);
        tgemm<2,true,true><<<gh, 256, TG_SMEM>>>(Y1h, W2h,
            nullptr, Y2h, b2, CHID, CHID, CHID, CHID, 0, 0, 0, 0, 1, 1.0f);
        tgemm<2,true,true><<<gh, 256, TG_SMEM>>>(Y2h, W3h,
            nullptr, Y1h, b3, CHID, CHID, CHID, CHID, 0, 0, 0, 0, 1, 1.0f);
        dim3 g4(CD / 256, MT / 128, 1);
        tgemm<0,true,false><<<g4, 256, TG_SMEM>>>(Y1h, W4h,
            AO, nullptr, b4, CHID, CHID, CHID, CD, 0, 0, 0, 0, 1, 1.0f);
    }
    // ---- out = LN(Z1 + ffn_out) ----
    add_ln_k<false><<<MT, 256>>>(Z1, AO, g2, be2, out, nullptr);
}